// round 14
// baseline (speedup 1.0000x reference)
#include <cuda_runtime.h>
#include <cuda_fp16.h>
#include <math_constants.h>

#define N_NODES 100000
#define N_EDGES 3200000
#define ED 128          // embed dim
#define NG 128          // num graphs
#define NC 10           // num classes
#define NB 129          // buckets = thresholds + 1
#define NHIST (NG * NB) // 16512
#define NSM 148         // persistent grid for edges2

typedef unsigned long long u64;

// Scratch (device globals; zero-init at module load).
// Invariants maintained by every kernel_launch call:
//   g_sd   : zero on entry (re-zeroed by k_bucket after consumption)
//   g_hist : zero on entry (re-zeroed by k_final after consumption)
//   g_cnt  : zero on entry (re-zeroed by k_final after consumption)
__device__ float         g_sd[N_NODES];      // edge-sum delta of s
__device__ __half        g_fh[N_NODES];      // half-precision feat (L1-friendly gather)
__device__ unsigned      g_e[N_NODES];       // enc24 (fixed-point s) <<8 | bucket
__device__ u64           g_hist[NHIST];      // global packed hist {sum<<24 | count}
__device__ int           g_cnt[NG];          // nodes per graph
__device__ float         g_T[ED];            // sorted thresholds
__device__ int           g_rank[ED];         // sorted position of threshold d
__device__ int           g_side[ED];         // 1: active = s > t (suffix); 0: prefix
__device__ int           g_bound[NG + 1];    // graph boundary table (gids sorted)

#define FP_SCALE 65536.0f
#define FP_BIAS  128.0f
#define FP_BIAS_FIX ((long long)(128 << 16))   // 2^23

// ---------------------------------------------------------------------------
// K0: prep — feat_h = half(feat); block 0: thresholds/rank/side;
//     block 1: graph boundary table from sorted gids.
__global__ __launch_bounds__(256) void k_prep(const float* __restrict__ feat,
                                              const int* __restrict__ gids,
                                              const float* __restrict__ W1,
                                              const float* __restrict__ b1) {
    int tid = threadIdx.x;
    int i = blockIdx.x * blockDim.x + tid;
    if (i < N_NODES) g_fh[i] = __float2half(feat[i]);

    if (blockIdx.x == 0) {
        __shared__ float ts[ED];
        if (tid < ED) {
            float w = W1[tid], b = b1[tid];
            float t; int side;
            if (w > 0.f)      { t = -b / w; side = 1; }
            else if (w < 0.f) { t = -b / w; side = 0; }
            else              { side = 1; t = (b > 0.f) ? -CUDART_INF_F : CUDART_INF_F; }
            ts[tid] = t;
            g_side[tid] = side;
        }
        __syncthreads();
        if (tid < ED) {
            float t = ts[tid];
            int r = 0;
#pragma unroll 8
            for (int j = 0; j < ED; j++) {
                float tj = ts[j];
                r += (tj < t) || (tj == t && j < tid);
            }
            g_rank[tid] = r;
            g_T[r] = t;
        }
    } else if (blockIdx.x == 1) {
        // bound[g] = first node index with gids >= g
        if (tid <= NG) {
            int g = tid;
            int lo = 0, hi = N_NODES;
            while (lo < hi) {
                int mid = (lo + hi) >> 1;
                if (__ldg(&gids[mid]) < g) lo = mid + 1; else hi = mid;
            }
            g_bound[g] = lo;
        }
    }
}

// ---------------------------------------------------------------------------
// K1: edge pass 1 — g_sd[dst] += feat_h[src]; 8 edges/thread, gathers batched.
__global__ __launch_bounds__(256) void k_edges1(const int4* __restrict__ src4,
                                                const int4* __restrict__ dst4) {
    const int half_n = N_EDGES / 8;   // 400000 int4 groups per half
    int i = blockIdx.x * blockDim.x + threadIdx.x;
    if (i >= half_n) return;
    int4 sa = __ldg(&src4[i]);
    int4 ta = __ldg(&dst4[i]);
    int4 sb = __ldg(&src4[i + half_n]);
    int4 tb = __ldg(&dst4[i + half_n]);
    float f0 = __half2float(__ldg(&g_fh[sa.x]));
    float f1 = __half2float(__ldg(&g_fh[sa.y]));
    float f2 = __half2float(__ldg(&g_fh[sa.z]));
    float f3 = __half2float(__ldg(&g_fh[sa.w]));
    float f4 = __half2float(__ldg(&g_fh[sb.x]));
    float f5 = __half2float(__ldg(&g_fh[sb.y]));
    float f6 = __half2float(__ldg(&g_fh[sb.z]));
    float f7 = __half2float(__ldg(&g_fh[sb.w]));
    atomicAdd(&g_sd[ta.x], f0);
    atomicAdd(&g_sd[ta.y], f1);
    atomicAdd(&g_sd[ta.z], f2);
    atomicAdd(&g_sd[ta.w], f3);
    atomicAdd(&g_sd[tb.x], f4);
    atomicAdd(&g_sd[tb.y], f5);
    atomicAdd(&g_sd[tb.z], f6);
    atomicAdd(&g_sd[tb.w], f7);
}

// ---------------------------------------------------------------------------
// K2: per node (scalar, 391 blocks — max parallelism for this latency-bound
//     kernel) — s = feat + g_sd (rezero g_sd); bucket search; encode;
//     self term into g_hist; per-graph counts.
__global__ __launch_bounds__(256) void k_bucket(const int* __restrict__ gids,
                                                const float* __restrict__ feat) {
    __shared__ float T[ED];
    __shared__ int hcnt[NG];
    int tid = threadIdx.x;
    if (tid < ED) T[tid] = g_T[tid];
    if (tid < NG) hcnt[tid] = 0;
    __syncthreads();
    int n = blockIdx.x * 256 + tid;
    if (n < N_NODES) {
        float s = feat[n] + g_sd[n];
        g_sd[n] = 0.0f;                       // restore zero invariant
        int b = 0;
#pragma unroll
        for (int st = 128; st > 0; st >>= 1) {
            int nb = b + st;
            if (nb <= ED && T[nb - 1] <= s) b = nb;
        }
        float sc = fminf(fmaxf(s, -FP_BIAS + 1.0f), FP_BIAS - 1.0f);
        unsigned enc = (unsigned)__float2int_rn((sc + FP_BIAS) * FP_SCALE);  // < 2^24
        g_e[n] = (enc << 8) | (unsigned)b;
        int g = gids[n];
        atomicAdd(&g_hist[g * NB + b], ((u64)enc << 24) | 1ull);
        atomicAdd(&hcnt[g], 1);
    }
    __syncthreads();
    if (tid < NG && hcnt[tid]) atomicAdd(&g_cnt[tid], hcnt[tid]);
}

// ---------------------------------------------------------------------------
// K3: edge pass 2 — 148 persistent CTAs x 1024 threads, smem-private hist.
//     gid(dst) via guided LDS walk over boundary table (no random gather).
__global__ __launch_bounds__(1024) void k_edges2(const int4* __restrict__ src4,
                                                 const int4* __restrict__ dst4) {
    extern __shared__ u64 sh[];
    u64* hist = sh;                           // NHIST u64 = 132096 B
    int* bnd = (int*)(sh + NHIST);            // NG+1 ints
    int tid = threadIdx.x;
    for (int i = tid; i < NHIST * 2; i += 1024) ((unsigned*)hist)[i] = 0u;
    if (tid <= NG) bnd[tid] = g_bound[tid];
    __syncthreads();

    const int half_n = N_EDGES / 8;           // 400000
    const int stride = gridDim.x * 1024;
#define EOP(e, t) {                                                    \
        int tt = (t);                                                  \
        int gg = (tt * NG) / N_NODES;                                  \
        while (bnd[gg + 1] <= tt) gg++;                                \
        while (bnd[gg] > tt) gg--;                                     \
        atomicAdd(&hist[gg * NB + (int)((e) & 0xFFu)],                 \
                  ((u64)((e) >> 8) << 24) | 1ull);                     \
    }
    for (int i = blockIdx.x * 1024 + tid; i < half_n; i += stride) {
        int4 sa = __ldg(&src4[i]);
        int4 ta = __ldg(&dst4[i]);
        int4 sb = __ldg(&src4[i + half_n]);
        int4 tb = __ldg(&dst4[i + half_n]);
        unsigned e0 = __ldg(&g_e[sa.x]);
        unsigned e1 = __ldg(&g_e[sa.y]);
        unsigned e2 = __ldg(&g_e[sa.z]);
        unsigned e3 = __ldg(&g_e[sa.w]);
        unsigned e4 = __ldg(&g_e[sb.x]);
        unsigned e5 = __ldg(&g_e[sb.y]);
        unsigned e6 = __ldg(&g_e[sb.z]);
        unsigned e7 = __ldg(&g_e[sb.w]);
        EOP(e0, ta.x);
        EOP(e1, ta.y);
        EOP(e2, ta.z);
        EOP(e3, ta.w);
        EOP(e4, tb.x);
        EOP(e5, tb.y);
        EOP(e6, tb.z);
        EOP(e7, tb.w);
    }
#undef EOP
    __syncthreads();
    // flush nonzero entries via global packed atomics
    for (int i = tid; i < NHIST; i += 1024) {
        u64 v = hist[i];
        if (v) atomicAdd(&g_hist[i], v);
    }
}

// ---------------------------------------------------------------------------
// K4: per graph — read + rezero g_hist, decode, suffix sums, hg, 3-layer head.
__global__ __launch_bounds__(128) void k_final(const float* __restrict__ W1,
                                               const float* __restrict__ b1,
                                               const float* __restrict__ W2,
                                               const float* __restrict__ b2,
                                               const float* __restrict__ Wf1,
                                               const float* __restrict__ bf1,
                                               const float* __restrict__ Wf2,
                                               const float* __restrict__ bf2,
                                               float* __restrict__ out) {
    __shared__ float bs[NB], bc[NB];
    __shared__ float suffS[NB + 1], suffC[NB + 1];
    __shared__ float a_sh[ED], h_sh[ED];
    __shared__ float invc_sh;
    int g = blockIdx.x;
    int d = threadIdx.x;

    if (d == 0) {
        int c = g_cnt[g];
        g_cnt[g] = 0;                          // restore zero invariant
        invc_sh = 1.0f / fmaxf((float)c, 1.0f);
    }
    for (int idx = d; idx < NB; idx += ED) {
        int off = g * NB + idx;
        u64 h = g_hist[off];
        g_hist[off] = 0ull;                    // restore zero invariant
        long long cnt = (long long)(h & 0xFFFFFFull);
        long long sfix = (long long)(h >> 24) - cnt * FP_BIAS_FIX;
        bs[idx] = (float)sfix * (1.0f / FP_SCALE);
        bc[idx] = (float)cnt;
    }
    __syncthreads();
    if (d == 0) {
        double as = 0.0, ac = 0.0;
        suffS[NB] = 0.f; suffC[NB] = 0.f;
        for (int k = NB - 1; k >= 0; k--) {
            as += (double)bs[k]; ac += (double)bc[k];
            suffS[k] = (float)as; suffC[k] = (float)ac;
        }
    }
    __syncthreads();

    // hg[g,d] = (W1[d]*S_active + b1[d]*C_active) / count[g]
    {
        float w = W1[d], b = b1[d];
        int r = g_rank[d];
        float S = suffS[r + 1], C = suffC[r + 1];
        if (!g_side[d]) { S = suffS[0] - S; C = suffC[0] - C; }
        a_sh[d] = (w * S + b * C) * invc_sh;
    }
    __syncthreads();

    float acc = b2[d];
#pragma unroll 8
    for (int k = 0; k < ED; k++) acc = fmaf(a_sh[k], W2[k * ED + d], acc);
    h_sh[d] = acc;
    __syncthreads();

    acc = bf1[d];
#pragma unroll 8
    for (int k = 0; k < ED; k++) acc = fmaf(h_sh[k], Wf1[k * ED + d], acc);
    acc = fmaxf(acc, 0.0f);
    __syncthreads();
    a_sh[d] = acc;
    __syncthreads();

    if (d < NC) {
        float o = bf2[d];
#pragma unroll 8
        for (int k = 0; k < ED; k++) o = fmaf(a_sh[k], Wf2[k * NC + d], o);
        out[g * NC + d] = o;
    }
}

// ---------------------------------------------------------------------------
extern "C" void kernel_launch(void* const* d_in, const int* in_sizes, int n_in,
                              void* d_out, int out_size) {
    const float* feat = (const float*)d_in[0];
    const int*   src  = (const int*)d_in[1];
    const int*   dst  = (const int*)d_in[2];
    const int*   gids = (const int*)d_in[3];
    const float* W1   = (const float*)d_in[4];
    const float* b1   = (const float*)d_in[5];
    const float* W2   = (const float*)d_in[6];
    const float* b2   = (const float*)d_in[7];
    const float* Wf1  = (const float*)d_in[8];
    const float* bf1  = (const float*)d_in[9];
    const float* Wf2  = (const float*)d_in[10];
    const float* bf2  = (const float*)d_in[11];
    float* out = (float*)d_out;

    const int smem_e2 = NHIST * sizeof(u64) + (NG + 2) * sizeof(int);
    static bool attr_done = false;
    if (!attr_done) {
        cudaFuncSetAttribute(k_edges2, cudaFuncAttributeMaxDynamicSharedMemorySize, smem_e2);
        attr_done = true;
    }

    k_prep<<<(N_NODES + 255) / 256, 256>>>(feat, gids, W1, b1);
    k_edges1<<<(N_EDGES / 8 + 255) / 256, 256>>>((const int4*)src, (const int4*)dst);
    k_bucket<<<(N_NODES + 255) / 256, 256>>>(gids, feat);
    k_edges2<<<NSM, 1024, smem_e2>>>((const int4*)src, (const int4*)dst);
    k_final<<<NG, ED>>>(W1, b1, W2, b2, Wf1, bf1, Wf2, bf2, out);
}

// round 15
// speedup vs baseline: 1.0496x; 1.0496x over previous
#include <cuda_runtime.h>
#include <math_constants.h>

#define N_NODES 100000
#define N_EDGES 3200000
#define ED 128          // embed dim
#define NG 128          // num graphs
#define NC 10           // num classes
#define NB 129          // buckets = thresholds + 1
#define NHIST (NG * NB) // 16512
#define NSM 148         // persistent grid for edges2

typedef unsigned long long u64;

// Scratch (device globals; zero-init at module load).
// Invariants maintained by every kernel_launch call:
//   g_sd   : zero on entry (re-zeroed by k_bucket after consumption)
//   g_hist : zero on entry (re-zeroed by k_final after consumption)
//   g_cnt  : zero on entry (re-zeroed by k_final after consumption)
__device__ float         g_sd[N_NODES];      // edge-sum delta of s
__device__ unsigned      g_e[N_NODES];       // enc16 (fixed-point s, scale 256) <<8 | bucket
__device__ u64           g_hist[NHIST];      // global packed hist {sum_enc16<<24 | count}
__device__ int           g_cnt[NG];          // nodes per graph
__device__ float         g_T[ED];            // sorted thresholds
__device__ int           g_rank[ED];         // sorted position of threshold d
__device__ int           g_side[ED];         // 1: active = s > t (suffix); 0: prefix
__device__ int           g_bound[NG + 1];    // graph boundary table (gids sorted)

#define FP_SCALE 256.0f                       // enc16 scale (step 1/256)
#define FP_BIAS  128.0f
// Σenc16 = FP_SCALE*ΣS + 32768*cnt  =>  ΣS = (Σenc16 - 32768*cnt)/256
#define FP_BIAS_FIX 32768LL

// ---------------------------------------------------------------------------
// K0: tiny prep (2 blocks) — block 0: thresholds/rank/side; block 1: bounds.
__global__ __launch_bounds__(256) void k_prep(const int* __restrict__ gids,
                                              const float* __restrict__ W1,
                                              const float* __restrict__ b1) {
    int tid = threadIdx.x;
    if (blockIdx.x == 0) {
        __shared__ float ts[ED];
        if (tid < ED) {
            float w = W1[tid], b = b1[tid];
            float t; int side;
            if (w > 0.f)      { t = -b / w; side = 1; }
            else if (w < 0.f) { t = -b / w; side = 0; }
            else              { side = 1; t = (b > 0.f) ? -CUDART_INF_F : CUDART_INF_F; }
            ts[tid] = t;
            g_side[tid] = side;
        }
        __syncthreads();
        if (tid < ED) {
            float t = ts[tid];
            int r = 0;
#pragma unroll 8
            for (int j = 0; j < ED; j++) {
                float tj = ts[j];
                r += (tj < t) || (tj == t && j < tid);
            }
            g_rank[tid] = r;
            g_T[r] = t;
        }
    } else {
        // bound[g] = first node index with gids >= g
        if (tid <= NG) {
            int g = tid;
            int lo = 0, hi = N_NODES;
            while (lo < hi) {
                int mid = (lo + hi) >> 1;
                if (__ldg(&gids[mid]) < g) lo = mid + 1; else hi = mid;
            }
            g_bound[g] = lo;
        }
    }
}

// ---------------------------------------------------------------------------
// K1: edge pass 1 — g_sd[dst] += feat[src]; 8 edges/thread, gathers batched.
__global__ __launch_bounds__(256) void k_edges1(const int4* __restrict__ src4,
                                                const int4* __restrict__ dst4,
                                                const float* __restrict__ feat) {
    const int half_n = N_EDGES / 8;   // 400000 int4 groups per half
    int i = blockIdx.x * blockDim.x + threadIdx.x;
    if (i >= half_n) return;
    int4 sa = __ldg(&src4[i]);
    int4 ta = __ldg(&dst4[i]);
    int4 sb = __ldg(&src4[i + half_n]);
    int4 tb = __ldg(&dst4[i + half_n]);
    float f0 = __ldg(&feat[sa.x]);
    float f1 = __ldg(&feat[sa.y]);
    float f2 = __ldg(&feat[sa.z]);
    float f3 = __ldg(&feat[sa.w]);
    float f4 = __ldg(&feat[sb.x]);
    float f5 = __ldg(&feat[sb.y]);
    float f6 = __ldg(&feat[sb.z]);
    float f7 = __ldg(&feat[sb.w]);
    atomicAdd(&g_sd[ta.x], f0);
    atomicAdd(&g_sd[ta.y], f1);
    atomicAdd(&g_sd[ta.z], f2);
    atomicAdd(&g_sd[ta.w], f3);
    atomicAdd(&g_sd[tb.x], f4);
    atomicAdd(&g_sd[tb.y], f5);
    atomicAdd(&g_sd[tb.z], f6);
    atomicAdd(&g_sd[tb.w], f7);
}

// ---------------------------------------------------------------------------
// K2: per node — s = feat + g_sd (rezero g_sd); bucket search; encode enc16;
//     self term into global g_hist (u64); per-graph counts.
__global__ __launch_bounds__(256) void k_bucket(const int* __restrict__ gids,
                                                const float* __restrict__ feat) {
    __shared__ float T[ED];
    __shared__ int hcnt[NG];
    int tid = threadIdx.x;
    if (tid < ED) T[tid] = g_T[tid];
    if (tid < NG) hcnt[tid] = 0;
    __syncthreads();
    int n = blockIdx.x * 256 + tid;
    if (n < N_NODES) {
        float s = feat[n] + g_sd[n];
        g_sd[n] = 0.0f;                       // restore zero invariant
        int b = 0;
#pragma unroll
        for (int st = 128; st > 0; st >>= 1) {
            int nb = b + st;
            if (nb <= ED && T[nb - 1] <= s) b = nb;
        }
        float sc = fminf(fmaxf(s, -FP_BIAS + 1.0f), FP_BIAS - 1.0f);
        unsigned enc = (unsigned)__float2int_rn((sc + FP_BIAS) * FP_SCALE);  // < 2^16
        g_e[n] = (enc << 8) | (unsigned)b;
        int g = gids[n];
        atomicAdd(&g_hist[g * NB + b], ((u64)enc << 24) | 1ull);
        atomicAdd(&hcnt[g], 1);
    }
    __syncthreads();
    if (tid < NG && hcnt[tid]) atomicAdd(&g_cnt[tid], hcnt[tid]);
}

// ---------------------------------------------------------------------------
// K3: edge pass 2 — 148 persistent CTAs x 1024 threads, smem-private u32 hist
//     {sum_enc16:24b | count:8b}; gid(dst) via guided LDS walk; flush widens
//     into global u64 g_hist.
__global__ __launch_bounds__(1024) void k_edges2(const int4* __restrict__ src4,
                                                 const int4* __restrict__ dst4) {
    extern __shared__ unsigned sh[];
    unsigned* hist = sh;                      // NHIST u32 = 66048 B
    int* bnd = (int*)(sh + NHIST);            // NG+1 ints
    int tid = threadIdx.x;
    for (int i = tid; i < NHIST; i += 1024) hist[i] = 0u;
    if (tid <= NG) bnd[tid] = g_bound[tid];
    __syncthreads();

    const int half_n = N_EDGES / 8;           // 400000
    const int stride = gridDim.x * 1024;
#define EOP(e, t) {                                                    \
        int tt = (t);                                                  \
        int gg = (tt * NG) / N_NODES;                                  \
        while (bnd[gg + 1] <= tt) gg++;                                \
        while (bnd[gg] > tt) gg--;                                     \
        atomicAdd(&hist[gg * NB + (int)((e) & 0xFFu)],                 \
                  ((e) & 0xFFFFFF00u) | 1u);                           \
    }
    for (int i = blockIdx.x * 1024 + tid; i < half_n; i += stride) {
        int4 sa = __ldg(&src4[i]);
        int4 ta = __ldg(&dst4[i]);
        int4 sb = __ldg(&src4[i + half_n]);
        int4 tb = __ldg(&dst4[i + half_n]);
        unsigned e0 = __ldg(&g_e[sa.x]);
        unsigned e1 = __ldg(&g_e[sa.y]);
        unsigned e2 = __ldg(&g_e[sa.z]);
        unsigned e3 = __ldg(&g_e[sa.w]);
        unsigned e4 = __ldg(&g_e[sb.x]);
        unsigned e5 = __ldg(&g_e[sb.y]);
        unsigned e6 = __ldg(&g_e[sb.z]);
        unsigned e7 = __ldg(&g_e[sb.w]);
        EOP(e0, ta.x);
        EOP(e1, ta.y);
        EOP(e2, ta.z);
        EOP(e3, ta.w);
        EOP(e4, tb.x);
        EOP(e5, tb.y);
        EOP(e6, tb.z);
        EOP(e7, tb.w);
    }
#undef EOP
    __syncthreads();
    // flush nonzero entries, widening {sum:24|cnt:8} -> global {sum:40|cnt:24}
    for (int i = tid; i < NHIST; i += 1024) {
        unsigned v = hist[i];
        if (v) atomicAdd(&g_hist[i], ((u64)(v >> 8) << 24) | (u64)(v & 0xFFu));
    }
}

// ---------------------------------------------------------------------------
// K4: per graph — read + rezero g_hist, decode, suffix sums, hg, 3-layer head.
__global__ __launch_bounds__(128) void k_final(const float* __restrict__ W1,
                                               const float* __restrict__ b1,
                                               const float* __restrict__ W2,
                                               const float* __restrict__ b2,
                                               const float* __restrict__ Wf1,
                                               const float* __restrict__ bf1,
                                               const float* __restrict__ Wf2,
                                               const float* __restrict__ bf2,
                                               float* __restrict__ out) {
    __shared__ float bs[NB], bc[NB];
    __shared__ float suffS[NB + 1], suffC[NB + 1];
    __shared__ float a_sh[ED], h_sh[ED];
    __shared__ float invc_sh;
    int g = blockIdx.x;
    int d = threadIdx.x;

    if (d == 0) {
        int c = g_cnt[g];
        g_cnt[g] = 0;                          // restore zero invariant
        invc_sh = 1.0f / fmaxf((float)c, 1.0f);
    }
    for (int idx = d; idx < NB; idx += ED) {
        int off = g * NB + idx;
        u64 h = g_hist[off];
        g_hist[off] = 0ull;                    // restore zero invariant
        long long cnt = (long long)(h & 0xFFFFFFull);
        long long sumq = (long long)(h >> 24);            // Σ enc16
        long long sfix = sumq - cnt * FP_BIAS_FIX;        // 256 * ΣS
        bs[idx] = (float)sfix * (1.0f / FP_SCALE);
        bc[idx] = (float)cnt;
    }
    __syncthreads();
    if (d == 0) {
        double as = 0.0, ac = 0.0;
        suffS[NB] = 0.f; suffC[NB] = 0.f;
        for (int k = NB - 1; k >= 0; k--) {
            as += (double)bs[k]; ac += (double)bc[k];
            suffS[k] = (float)as; suffC[k] = (float)ac;
        }
    }
    __syncthreads();

    // hg[g,d] = (W1[d]*S_active + b1[d]*C_active) / count[g]
    {
        float w = W1[d], b = b1[d];
        int r = g_rank[d];
        float S = suffS[r + 1], C = suffC[r + 1];
        if (!g_side[d]) { S = suffS[0] - S; C = suffC[0] - C; }
        a_sh[d] = (w * S + b * C) * invc_sh;
    }
    __syncthreads();

    float acc = b2[d];
#pragma unroll 8
    for (int k = 0; k < ED; k++) acc = fmaf(a_sh[k], W2[k * ED + d], acc);
    h_sh[d] = acc;
    __syncthreads();

    acc = bf1[d];
#pragma unroll 8
    for (int k = 0; k < ED; k++) acc = fmaf(h_sh[k], Wf1[k * ED + d], acc);
    acc = fmaxf(acc, 0.0f);
    __syncthreads();
    a_sh[d] = acc;
    __syncthreads();

    if (d < NC) {
        float o = bf2[d];
#pragma unroll 8
        for (int k = 0; k < ED; k++) o = fmaf(a_sh[k], Wf2[k * NC + d], o);
        out[g * NC + d] = o;
    }
}

// ---------------------------------------------------------------------------
extern "C" void kernel_launch(void* const* d_in, const int* in_sizes, int n_in,
                              void* d_out, int out_size) {
    const float* feat = (const float*)d_in[0];
    const int*   src  = (const int*)d_in[1];
    const int*   dst  = (const int*)d_in[2];
    const int*   gids = (const int*)d_in[3];
    const float* W1   = (const float*)d_in[4];
    const float* b1   = (const float*)d_in[5];
    const float* W2   = (const float*)d_in[6];
    const float* b2   = (const float*)d_in[7];
    const float* Wf1  = (const float*)d_in[8];
    const float* bf1  = (const float*)d_in[9];
    const float* Wf2  = (const float*)d_in[10];
    const float* bf2  = (const float*)d_in[11];
    float* out = (float*)d_out;

    const int smem_e2 = NHIST * sizeof(unsigned) + (NG + 2) * sizeof(int);
    static bool attr_done = false;
    if (!attr_done) {
        cudaFuncSetAttribute(k_edges2, cudaFuncAttributeMaxDynamicSharedMemorySize, smem_e2);
        attr_done = true;
    }

    k_prep<<<2, 256>>>(gids, W1, b1);
    k_edges1<<<(N_EDGES / 8 + 255) / 256, 256>>>((const int4*)src, (const int4*)dst, feat);
    k_bucket<<<(N_NODES + 255) / 256, 256>>>(gids, feat);
    k_edges2<<<NSM, 1024, smem_e2>>>((const int4*)src, (const int4*)dst);
    k_final<<<NG, ED>>>(W1, b1, W2, b2, Wf1, bf1, Wf2, bf2, out);
}